// round 13
// baseline (speedup 1.0000x reference)
#include <cuda_runtime.h>
#include <cuda_fp16.h>
#include <cuda_bf16.h>

// MonotoneActivation: B=4096, G=512, K=4, D=8
// out[b,g,d] = sum_k coef_k * params[g, j_k, d]
//   v0<=v1<=v2<=v3 sorted values of X[b,g,:], coef=[v0,v1-v0,v2-v1,v3-v2]
//   j_0 = 15,  j_k = bitmask{ i : A_i >= v_k }  (ties give c_k = 0, so any
//   extra mask bits under ties are multiplied by exactly zero).
//
// R11 lessons: nothing saturated (L1 55%, issue 46%) -> instruction-count +
// wave-tail bound. This round: packed fma.rn.f32x2 (32 FFMA -> 16 FFMA2),
// direct >=-masks instead of rank pipeline, TB=16 for fine-grained blocks.

#define B_DIM 4096
#define G_DIM 512
#define TG 64            // g-tables per block
#define TB 16            // b-rows per block
#define THREADS 256
#define TSTRIDE_B 272    // bytes per fp16 table: 16 rows * 16B + 16B pad

typedef unsigned long long u64;

static __device__ __forceinline__ u64 f32x2_pack(float lo, float hi) {
    u64 r; asm("mov.b64 %0, {%1, %2};" : "=l"(r) : "f"(lo), "f"(hi)); return r;
}
static __device__ __forceinline__ u64 f32x2_mul(u64 a, u64 b) {
    u64 d; asm("mul.rn.f32x2 %0, %1, %2;" : "=l"(d) : "l"(a), "l"(b)); return d;
}
static __device__ __forceinline__ u64 f32x2_fma(u64 a, u64 b, u64 c) {
    u64 d; asm("fma.rn.f32x2 %0, %1, %2, %3;" : "=l"(d) : "l"(a), "l"(b), "l"(c)); return d;
}
static __device__ __forceinline__ float2 f32x2_unpack(u64 v) {
    float2 f; asm("mov.b64 {%0, %1}, %2;" : "=f"(f.x), "=f"(f.y) : "l"(v)); return f;
}
// half2 bits -> packed f32x2 (two F2F.F32.F16 in SASS; fixed-lat alu class)
static __device__ __forceinline__ u64 h2_to_f32x2(unsigned h) {
    u64 r;
    asm("{\n\t"
        ".reg .b16 l16, h16;\n\t"
        ".reg .f32 lo, hi;\n\t"
        "mov.b32 {l16, h16}, %1;\n\t"
        "cvt.f32.f16 lo, l16;\n\t"
        "cvt.f32.f16 hi, h16;\n\t"
        "mov.b64 %0, {lo, hi};\n\t"
        "}" : "=l"(r) : "r"(h));
    return r;
}
static __device__ __forceinline__ unsigned h2_bits(__half2 h) {
    return *reinterpret_cast<unsigned*>(&h);
}

__global__ __launch_bounds__(THREADS, 5)
void monotone_act_kernel(const float* __restrict__ X,
                         const float* __restrict__ P,
                         float* __restrict__ out)
{
    __shared__ __align__(16) unsigned char sPB[TG * TSTRIDE_B];   // 17408 B

    const int g0 = blockIdx.x * TG;
    const int b0 = blockIdx.y * TB;

    // ---- stage TG param tables, fp32 -> fp16 ----
    const float4* Pv = reinterpret_cast<const float4*>(P + (size_t)g0 * 128);
    #pragma unroll
    for (int i = threadIdx.x; i < TG * 32; i += THREADS) {
        float4 v = __ldg(&Pv[i]);
        __half2 h01 = __floats2half2_rn(v.x, v.y);
        __half2 h23 = __floats2half2_rn(v.z, v.w);
        int gt = i >> 5;
        int w4 = i & 31;
        uint2 u;
        u.x = h2_bits(h01);
        u.y = h2_bits(h23);
        *reinterpret_cast<uint2*>(&sPB[gt * TSTRIDE_B + w4 * 8]) = u;
    }
    __syncthreads();

    const int gl = threadIdx.x & (TG - 1);       // 0..63 (consecutive g in warp)
    const int bl = threadIdx.x >> 6;             // 0..3
    const uint4* tab = reinterpret_cast<const uint4*>(&sPB[gl * TSTRIDE_B]);

    // row 15 used by every pair -> packed f32x2 registers
    u64 f15[4];
    {
        uint4 r = tab[15];
        f15[0] = h2_to_f32x2(r.x);
        f15[1] = h2_to_f32x2(r.y);
        f15[2] = h2_to_f32x2(r.z);
        f15[3] = h2_to_f32x2(r.w);
    }

    const float4* Xv = reinterpret_cast<const float4*>(X);
    float4*       Ov = reinterpret_cast<float4*>(out);

    const int t0 = ((b0 + bl) << 9) + g0 + gl;

    // preload all 4 X vectors (deep MLP, xv only -> modest regs)
    float4 xv[4];
    #pragma unroll
    for (int u = 0; u < 4; ++u)
        xv[u] = __ldcs(&Xv[t0 + ((u * 4) << 9)]);

    #pragma unroll
    for (int u = 0; u < 4; ++u) {
        const int t = t0 + ((u * 4) << 9);
        const float a0 = xv[u].x, a1 = xv[u].y, a2 = xv[u].z, a3 = xv[u].w;

        // ---- sorted values via min/max network ----
        float m0 = fminf(a0, a1), M0 = fmaxf(a0, a1);
        float m1 = fminf(a2, a3), M1 = fmaxf(a2, a3);
        float v0 = fminf(m0, m1), tm = fmaxf(m0, m1);
        float v3 = fmaxf(M0, M1), sm = fminf(M0, M1);
        float v1 = fminf(tm, sm), v2 = fmaxf(tm, sm);

        const float c0 = v0;
        const float c1 = v1 - v0;
        const float c2 = v2 - v1;
        const float c3 = v3 - v2;

        // ---- direct gather masks: bit i of j_k = (a_i >= v_k) ----
        const int j1 = (int)(a0 >= v1) | ((int)(a1 >= v1) << 1)
                     | ((int)(a2 >= v1) << 2) | ((int)(a3 >= v1) << 3);
        const int j2 = (int)(a0 >= v2) | ((int)(a1 >= v2) << 1)
                     | ((int)(a2 >= v2) << 2) | ((int)(a3 >= v2) << 3);
        const int j3 = (int)(a0 >= v3) | ((int)(a1 >= v3) << 1)
                     | ((int)(a2 >= v3) << 2) | ((int)(a3 >= v3) << 3);

        // ---- fp16 row gathers: one LDS.128 per row ----
        uint4 q1 = tab[j1];
        uint4 q2 = tab[j2];
        uint4 q3 = tab[j3];

        // ---- packed f32x2 accumulation ----
        const u64 c0x = f32x2_pack(c0, c0);
        const u64 c1x = f32x2_pack(c1, c1);
        const u64 c2x = f32x2_pack(c2, c2);
        const u64 c3x = f32x2_pack(c3, c3);

        u64 acc0 = f32x2_mul(c0x, f15[0]);
        u64 acc1 = f32x2_mul(c0x, f15[1]);
        u64 acc2 = f32x2_mul(c0x, f15[2]);
        u64 acc3 = f32x2_mul(c0x, f15[3]);

        acc0 = f32x2_fma(c1x, h2_to_f32x2(q1.x), acc0);
        acc1 = f32x2_fma(c1x, h2_to_f32x2(q1.y), acc1);
        acc2 = f32x2_fma(c1x, h2_to_f32x2(q1.z), acc2);
        acc3 = f32x2_fma(c1x, h2_to_f32x2(q1.w), acc3);

        acc0 = f32x2_fma(c2x, h2_to_f32x2(q2.x), acc0);
        acc1 = f32x2_fma(c2x, h2_to_f32x2(q2.y), acc1);
        acc2 = f32x2_fma(c2x, h2_to_f32x2(q2.z), acc2);
        acc3 = f32x2_fma(c2x, h2_to_f32x2(q2.w), acc3);

        acc0 = f32x2_fma(c3x, h2_to_f32x2(q3.x), acc0);
        acc1 = f32x2_fma(c3x, h2_to_f32x2(q3.y), acc1);
        acc2 = f32x2_fma(c3x, h2_to_f32x2(q3.z), acc2);
        acc3 = f32x2_fma(c3x, h2_to_f32x2(q3.w), acc3);

        float2 o0 = f32x2_unpack(acc0);
        float2 o1 = f32x2_unpack(acc1);
        float2 o2 = f32x2_unpack(acc2);
        float2 o3 = f32x2_unpack(acc3);

        float4 lo, hi;
        lo.x = o0.x; lo.y = o0.y; lo.z = o1.x; lo.w = o1.y;
        hi.x = o2.x; hi.y = o2.y; hi.z = o3.x; hi.w = o3.y;

        __stcs(&Ov[t * 2],     lo);
        __stcs(&Ov[t * 2 + 1], hi);
    }
}

extern "C" void kernel_launch(void* const* d_in, const int* in_sizes, int n_in,
                              void* d_out, int out_size)
{
    const float* X = (const float*)d_in[0];   // (4096, 2048) f32
    const float* P = (const float*)d_in[1];   // (512, 16, 8)  f32
    float* out     = (float*)d_out;           // (4096, 4096) f32

    dim3 grid(G_DIM / TG, B_DIM / TB);        // (8, 256) = 2048 blocks
    monotone_act_kernel<<<grid, THREADS>>>(X, P, out);
}

// round 14
// speedup vs baseline: 1.0707x; 1.0707x over previous
#include <cuda_runtime.h>
#include <cuda_fp16.h>
#include <cuda_bf16.h>

// MonotoneActivation: B=4096, G=512, K=4, D=8
// out[b,g,d] = sum_k coef_k * params[g, j_k, d]
//   v0<=v1<=v2<=v3 sorted values of X[b,g,:], coef=[v0,v1-v0,v2-v1,v3-v2]
//   j_0 = 15,  j_k = bitmask{ i : A_i >= v_k }  (tie bits hit zero coef).
//
// R13 lesson: TB=16 doubled staging traffic (64MB L2) and regressed.
// This round: TB=32 (R11 config) + direct masks + packed f32x2 FMA.

#define B_DIM 4096
#define G_DIM 512
#define TG 64            // g-tables per block
#define TB 32            // b-rows per block
#define THREADS 256
#define TSTRIDE_B 272    // bytes per fp16 table: 16 rows * 16B + 16B pad

typedef unsigned long long u64;

static __device__ __forceinline__ u64 f32x2_pack(float lo, float hi) {
    u64 r; asm("mov.b64 %0, {%1, %2};" : "=l"(r) : "f"(lo), "f"(hi)); return r;
}
static __device__ __forceinline__ u64 f32x2_mul(u64 a, u64 b) {
    u64 d; asm("mul.rn.f32x2 %0, %1, %2;" : "=l"(d) : "l"(a), "l"(b)); return d;
}
static __device__ __forceinline__ u64 f32x2_fma(u64 a, u64 b, u64 c) {
    u64 d; asm("fma.rn.f32x2 %0, %1, %2, %3;" : "=l"(d) : "l"(a), "l"(b), "l"(c)); return d;
}
static __device__ __forceinline__ float2 f32x2_unpack(u64 v) {
    float2 f; asm("mov.b64 {%0, %1}, %2;" : "=f"(f.x), "=f"(f.y) : "l"(v)); return f;
}
static __device__ __forceinline__ u64 h2_to_f32x2(unsigned h) {
    u64 r;
    asm("{\n\t"
        ".reg .b16 l16, h16;\n\t"
        ".reg .f32 lo, hi;\n\t"
        "mov.b32 {l16, h16}, %1;\n\t"
        "cvt.f32.f16 lo, l16;\n\t"
        "cvt.f32.f16 hi, h16;\n\t"
        "mov.b64 %0, {lo, hi};\n\t"
        "}" : "=l"(r) : "r"(h));
    return r;
}
static __device__ __forceinline__ unsigned h2_bits(__half2 h) {
    return *reinterpret_cast<unsigned*>(&h);
}

__global__ __launch_bounds__(THREADS, 5)
void monotone_act_kernel(const float* __restrict__ X,
                         const float* __restrict__ P,
                         float* __restrict__ out)
{
    __shared__ __align__(16) unsigned char sPB[TG * TSTRIDE_B];   // 17408 B

    const int g0 = blockIdx.x * TG;
    const int b0 = blockIdx.y * TB;

    // ---- stage TG param tables, fp32 -> fp16 ----
    const float4* Pv = reinterpret_cast<const float4*>(P + (size_t)g0 * 128);
    #pragma unroll
    for (int i = threadIdx.x; i < TG * 32; i += THREADS) {
        float4 v = __ldg(&Pv[i]);
        __half2 h01 = __floats2half2_rn(v.x, v.y);
        __half2 h23 = __floats2half2_rn(v.z, v.w);
        int gt = i >> 5;
        int w4 = i & 31;
        uint2 u;
        u.x = h2_bits(h01);
        u.y = h2_bits(h23);
        *reinterpret_cast<uint2*>(&sPB[gt * TSTRIDE_B + w4 * 8]) = u;
    }
    __syncthreads();

    const int gl = threadIdx.x & (TG - 1);       // 0..63 (consecutive g in warp)
    const int bl = threadIdx.x >> 6;             // 0..3
    const uint4* tab = reinterpret_cast<const uint4*>(&sPB[gl * TSTRIDE_B]);

    // row 15 used by every pair -> packed f32x2 registers
    u64 f15[4];
    {
        uint4 r = tab[15];
        f15[0] = h2_to_f32x2(r.x);
        f15[1] = h2_to_f32x2(r.y);
        f15[2] = h2_to_f32x2(r.z);
        f15[3] = h2_to_f32x2(r.w);
    }

    const float4* Xv = reinterpret_cast<const float4*>(X);
    float4*       Ov = reinterpret_cast<float4*>(out);

    const int t0 = ((b0 + bl) << 9) + g0 + gl;
    float4 xv_next = __ldcs(&Xv[t0]);

    #pragma unroll
    for (int it = 0; it < TB / 4; ++it) {
        const int t = t0 + ((it * 4) << 9);
        float4 xv = xv_next;
        if (it < TB / 4 - 1)
            xv_next = __ldcs(&Xv[t + (4 << 9)]);

        const float a0 = xv.x, a1 = xv.y, a2 = xv.z, a3 = xv.w;

        // ---- sorted values via min/max network ----
        float m0 = fminf(a0, a1), M0 = fmaxf(a0, a1);
        float m1 = fminf(a2, a3), M1 = fmaxf(a2, a3);
        float v0 = fminf(m0, m1), tm = fmaxf(m0, m1);
        float v3 = fmaxf(M0, M1), sm = fminf(M0, M1);
        float v1 = fminf(tm, sm), v2 = fmaxf(tm, sm);

        const float c0 = v0;
        const float c1 = v1 - v0;
        const float c2 = v2 - v1;
        const float c3 = v3 - v2;

        // ---- direct gather masks: bit i of j_k = (a_i >= v_k) ----
        const int j1 = (int)(a0 >= v1) | ((int)(a1 >= v1) << 1)
                     | ((int)(a2 >= v1) << 2) | ((int)(a3 >= v1) << 3);
        const int j2 = (int)(a0 >= v2) | ((int)(a1 >= v2) << 1)
                     | ((int)(a2 >= v2) << 2) | ((int)(a3 >= v2) << 3);
        const int j3 = (int)(a0 >= v3) | ((int)(a1 >= v3) << 1)
                     | ((int)(a2 >= v3) << 2) | ((int)(a3 >= v3) << 3);

        // ---- fp16 row gathers: one LDS.128 per row ----
        uint4 q1 = tab[j1];
        uint4 q2 = tab[j2];
        uint4 q3 = tab[j3];

        // ---- packed f32x2 accumulation ----
        const u64 c0x = f32x2_pack(c0, c0);
        const u64 c1x = f32x2_pack(c1, c1);
        const u64 c2x = f32x2_pack(c2, c2);
        const u64 c3x = f32x2_pack(c3, c3);

        u64 acc0 = f32x2_mul(c0x, f15[0]);
        u64 acc1 = f32x2_mul(c0x, f15[1]);
        u64 acc2 = f32x2_mul(c0x, f15[2]);
        u64 acc3 = f32x2_mul(c0x, f15[3]);

        acc0 = f32x2_fma(c1x, h2_to_f32x2(q1.x), acc0);
        acc1 = f32x2_fma(c1x, h2_to_f32x2(q1.y), acc1);
        acc2 = f32x2_fma(c1x, h2_to_f32x2(q1.z), acc2);
        acc3 = f32x2_fma(c1x, h2_to_f32x2(q1.w), acc3);

        acc0 = f32x2_fma(c2x, h2_to_f32x2(q2.x), acc0);
        acc1 = f32x2_fma(c2x, h2_to_f32x2(q2.y), acc1);
        acc2 = f32x2_fma(c2x, h2_to_f32x2(q2.z), acc2);
        acc3 = f32x2_fma(c2x, h2_to_f32x2(q2.w), acc3);

        acc0 = f32x2_fma(c3x, h2_to_f32x2(q3.x), acc0);
        acc1 = f32x2_fma(c3x, h2_to_f32x2(q3.y), acc1);
        acc2 = f32x2_fma(c3x, h2_to_f32x2(q3.z), acc2);
        acc3 = f32x2_fma(c3x, h2_to_f32x2(q3.w), acc3);

        float2 o0 = f32x2_unpack(acc0);
        float2 o1 = f32x2_unpack(acc1);
        float2 o2 = f32x2_unpack(acc2);
        float2 o3 = f32x2_unpack(acc3);

        float4 lo, hi;
        lo.x = o0.x; lo.y = o0.y; lo.z = o1.x; lo.w = o1.y;
        hi.x = o2.x; hi.y = o2.y; hi.z = o3.x; hi.w = o3.y;

        __stcs(&Ov[t * 2],     lo);
        __stcs(&Ov[t * 2 + 1], hi);
    }
}

extern "C" void kernel_launch(void* const* d_in, const int* in_sizes, int n_in,
                              void* d_out, int out_size)
{
    const float* X = (const float*)d_in[0];   // (4096, 2048) f32
    const float* P = (const float*)d_in[1];   // (512, 16, 8)  f32
    float* out     = (float*)d_out;           // (4096, 4096) f32

    dim3 grid(G_DIM / TG, B_DIM / TB);        // (8, 128) = 1024 blocks
    monotone_act_kernel<<<grid, THREADS>>>(X, P, out);
}